// round 3
// baseline (speedup 1.0000x reference)
#include <cuda_runtime.h>
#include <math.h>
#include <stdint.h>

#define NTOK  32768
#define CH    128
#define CF    512
#define JQKV  384
#define NHEADS 8
#define HD    16

// weight-split buffer offsets (in uint2 elements)
#define OFF_QKV  0
#define OFF_PROJ 49152
#define OFF_FFN1 65536
#define OFF_FFN2 131072
#define NWSPLIT  196608

// ---------------- scratch (device globals; no runtime allocation) ----------------
__device__ float g_qkv[NTOK * JQKV];   // (N, 384) row-major
__device__ float g_attn[NTOK * CH];    // (N, 128)
__device__ float g_y[NTOK * CH];       // proj out (N, 128)
__device__ float g_h[NTOK * CF];       // ffn hidden (N, 512)
__device__ float g_z[NTOK * CH];       // ffn out + residual (N, 128)
__device__ uint2 g_wsplit[NWSPLIT];    // all weights pre-split to tf32 hi/lo
__device__ float g_sum1[CH], g_sq1[CH], g_sum2[CH], g_sq2[CH];
__device__ float g_m1[CH], g_i1[CH], g_m2[CH], g_i2[CH];

// ---------------- zero stats ----------------
__global__ void zero_stats_kernel() {
    int t = threadIdx.x;
    if (t < CH) { g_sum1[t] = 0.f; g_sq1[t] = 0.f; g_sum2[t] = 0.f; g_sq2[t] = 0.f; }
}

// ---------------- TF32 helpers ----------------
__device__ __forceinline__ uint2 split_tf32(float x) {
    uint32_t h;
    asm("cvt.rna.tf32.f32 %0, %1;" : "=r"(h) : "f"(x));
    float hf = __uint_as_float(h);
    uint32_t l;
    asm("cvt.rna.tf32.f32 %0, %1;" : "=r"(l) : "f"(x - hf));
    return make_uint2(h, l);
}

__device__ __forceinline__ void mma_tf32(float c[4], const uint32_t a[4], const uint32_t b[2]) {
    asm volatile(
        "mma.sync.aligned.m16n8k8.row.col.f32.tf32.tf32.f32 "
        "{%0,%1,%2,%3}, {%4,%5,%6,%7}, {%8,%9}, {%0,%1,%2,%3};\n"
        : "+f"(c[0]), "+f"(c[1]), "+f"(c[2]), "+f"(c[3])
        : "r"(a[0]), "r"(a[1]), "r"(a[2]), "r"(a[3]), "r"(b[0]), "r"(b[1]));
}

// ---------------- weight pre-split: all four matrices -> g_wsplit ----------------
__global__ void split_weights_kernel(const float* __restrict__ wqkv,
                                     const float* __restrict__ wproj,
                                     const float* __restrict__ wffn1,
                                     const float* __restrict__ wffn2)
{
    int idx = blockIdx.x * 256 + threadIdx.x;
    if (idx >= NWSPLIT) return;
    float v;
    if (idx < OFF_PROJ)      v = wqkv[idx - OFF_QKV];
    else if (idx < OFF_FFN1) v = wproj[idx - OFF_PROJ];
    else if (idx < OFF_FFN2) v = wffn1[idx - OFF_FFN1];
    else                     v = wffn2[idx - OFF_FFN2];
    g_wsplit[idx] = split_tf32(v);
}

// ---------------- tensor-core TF32 GEMM, pre-split smem, xor-swizzled ----------------
// out[m][j] = sum_k A * W[j][k] + bias[j]
// AKM: A stored (K, M); else (M, K). NORMA: normalize A on load (per-k mean/istd).
// EPI: 0 = bias; 1 = gelu(acc+bias); 2 = acc+bias + norm(res[m][j])
// 128 threads (4 warps), BM=128, BN=64, BK=32, warp tile 64x32.
template<bool AKM, bool NORMA, int EPI>
__global__ void __launch_bounds__(128) gemm_tc(const float* __restrict__ A,
                                               const uint2* __restrict__ Wsp,
                                               const float* __restrict__ bias,
                                               float* __restrict__ out,
                                               int M, int Kd, int Jd,
                                               const float* __restrict__ nmean,
                                               const float* __restrict__ nistd,
                                               const float* __restrict__ res)
{
    __shared__ uint2 As2[32 * 128];   // 32 KB: As2[k*128 + (m ^ ((k&3)<<2))]
    __shared__ uint2 Bs2[32 * 64];    // 16 KB: Bs2[k*64  + (n ^ ((k&3)<<2))]

    const int tid  = threadIdx.x;
    const int wid  = tid >> 5, lane = tid & 31;
    const int l4   = lane >> 2, q = lane & 3;
    const int xq   = q << 2;
    const int wm   = wid & 1, wn = wid >> 1;       // warp tile: rows wm*64, cols wn*32
    const int m0   = blockIdx.x * 128, j0 = blockIdx.y * 64;

    float c[4][4][4];
    #pragma unroll
    for (int mi = 0; mi < 4; mi++)
        #pragma unroll
        for (int ni = 0; ni < 4; ni++)
            #pragma unroll
            for (int r = 0; r < 4; r++) c[mi][ni][r] = 0.f;

    for (int k0 = 0; k0 < Kd; k0 += 32) {
        // ---- stage A tile (32 x 128), split to hi/lo ----
        if (AKM) {
            #pragma unroll
            for (int i = 0; i < 8; i++) {
                int kk = wid * 8 + i;
                const float* src = &A[(size_t)(k0 + kk) * M + m0];
                int xk = (kk & 3) << 2;
                #pragma unroll
                for (int cc = 0; cc < 4; cc++) {
                    int mm = lane + 32 * cc;
                    As2[kk * 128 + (mm ^ xk)] = split_tf32(src[mm]);
                }
            }
        } else {
            const int mm = tid;
            const float* src = &A[(size_t)(m0 + mm) * Kd + k0];
            #pragma unroll
            for (int cc = 0; cc < 8; cc++) {
                float4 t4 = *(const float4*)(src + cc * 4);
                if (NORMA) {
                    int kb = k0 + cc * 4;
                    t4.x = (t4.x - nmean[kb + 0]) * nistd[kb + 0];
                    t4.y = (t4.y - nmean[kb + 1]) * nistd[kb + 1];
                    t4.z = (t4.z - nmean[kb + 2]) * nistd[kb + 2];
                    t4.w = (t4.w - nmean[kb + 3]) * nistd[kb + 3];
                }
                int k = cc * 4;
                As2[(k + 0) * 128 + (mm ^ (((k + 0) & 3) << 2))] = split_tf32(t4.x);
                As2[(k + 1) * 128 + (mm ^ (((k + 1) & 3) << 2))] = split_tf32(t4.y);
                As2[(k + 2) * 128 + (mm ^ (((k + 2) & 3) << 2))] = split_tf32(t4.z);
                As2[(k + 3) * 128 + (mm ^ (((k + 3) & 3) << 2))] = split_tf32(t4.w);
            }
        }
        // ---- stage B tile (32 x 64): pre-split weights, pure copy ----
        {
            const int nn = tid >> 1, half = tid & 1;
            const uint2* src = &Wsp[(size_t)(j0 + nn) * Kd + k0 + half * 16];
            #pragma unroll
            for (int cc = 0; cc < 8; cc++) {
                uint4 t = *(const uint4*)(src + cc * 2);      // elems k, k+1
                int k = half * 16 + cc * 2;
                Bs2[(k + 0) * 64 + (nn ^ (((k + 0) & 3) << 2))] = make_uint2(t.x, t.y);
                Bs2[(k + 1) * 64 + (nn ^ (((k + 1) & 3) << 2))] = make_uint2(t.z, t.w);
            }
        }
        __syncthreads();

        #pragma unroll
        for (int g = 0; g < 4; g++) {
            const int kA = (g * 8 + q) * 128;
            const int kA4 = (g * 8 + q + 4) * 128;
            const int kB = (g * 8 + q) * 64;
            const int kB4 = (g * 8 + q + 4) * 64;
            uint32_t bh[4][2], bl[4][2];
            #pragma unroll
            for (int ni = 0; ni < 4; ni++) {
                int col = (wn * 32 + ni * 8 + l4) ^ xq;
                uint2 u0 = Bs2[kB + col];
                uint2 u1 = Bs2[kB4 + col];
                bh[ni][0] = u0.x; bl[ni][0] = u0.y;
                bh[ni][1] = u1.x; bl[ni][1] = u1.y;
            }
            #pragma unroll
            for (int mi = 0; mi < 4; mi++) {
                int r0 = wm * 64 + mi * 16 + l4;
                uint2 a0 = As2[kA  + (r0 ^ xq)];
                uint2 a1 = As2[kA  + ((r0 + 8) ^ xq)];
                uint2 a2 = As2[kA4 + (r0 ^ xq)];
                uint2 a3 = As2[kA4 + ((r0 + 8) ^ xq)];
                uint32_t ah[4] = {a0.x, a1.x, a2.x, a3.x};
                uint32_t al[4] = {a0.y, a1.y, a2.y, a3.y};
                #pragma unroll
                for (int ni = 0; ni < 4; ni++) {
                    mma_tf32(c[mi][ni], ah, bh[ni]);   // hi*hi
                    mma_tf32(c[mi][ni], al, bh[ni]);   // lo*hi
                    mma_tf32(c[mi][ni], ah, bl[ni]);   // hi*lo
                }
            }
        }
        __syncthreads();
    }

    // ---- epilogue ----
    #pragma unroll
    for (int ni = 0; ni < 4; ni++) {
        int j = j0 + wn * 32 + ni * 8 + q * 2;
        float b0 = bias[j], b1 = bias[j + 1];
        float im0 = 0.f, ii0 = 0.f, im1 = 0.f, ii1 = 0.f;
        if (EPI == 2) { im0 = nmean[j]; ii0 = nistd[j]; im1 = nmean[j + 1]; ii1 = nistd[j + 1]; }
        #pragma unroll
        for (int mi = 0; mi < 4; mi++) {
            int r0 = m0 + wm * 64 + mi * 16 + l4;
            #pragma unroll
            for (int half = 0; half < 2; half++) {
                int m = r0 + half * 8;
                float v0 = c[mi][ni][half * 2 + 0] + b0;
                float v1 = c[mi][ni][half * 2 + 1] + b1;
                if (EPI == 1) {
                    float u = v0;
                    v0 = 0.5f * u * (1.f + tanhf(0.7978845608028654f * (u + 0.044715f * u * u * u)));
                    u = v1;
                    v1 = 0.5f * u * (1.f + tanhf(0.7978845608028654f * (u + 0.044715f * u * u * u)));
                } else if (EPI == 2) {
                    float2 r2 = *(const float2*)&res[(size_t)m * Jd + j];
                    v0 += (r2.x - im0) * ii0;
                    v1 += (r2.y - im1) * ii1;
                }
                *(float2*)&out[(size_t)m * Jd + j] = make_float2(v0, v1);
            }
        }
    }
}

// ---------------- neighborhood attention: one warp per token ----------------
__global__ void attn_kernel(const float* __restrict__ qkv, const float* __restrict__ rpb,
                            float* __restrict__ out)
{
    __shared__ float rpb_s[NHEADS * 125];
    const int tid = threadIdx.x;
    for (int i = tid; i < NHEADS * 125; i += 256) rpb_s[i] = rpb[i];
    __syncthreads();

    const int warp = tid >> 5, lane = tid & 31;
    const int n = blockIdx.x * 8 + warp;
    const int h = lane >> 2, p = lane & 3;

    const int hh = n >> 10, ww = (n >> 5) & 31, zz = n & 31;
    const int sh = min(max(hh - 1, 0), 29);
    const int sw = min(max(ww - 1, 0), 29);
    const int sz = min(max(zz - 1, 0), 29);
    const int bh = sh - hh + 2, bw = sw - ww + 2, bz = sz - zz + 2;

    float4 q4 = *(const float4*)&qkv[(size_t)n * JQKV + h * 16 + p * 4];
    const float qx = q4.x * 0.25f, qy = q4.y * 0.25f, qz = q4.z * 0.25f, qw = q4.w * 0.25f;

    const float* rb = &rpb_s[h * 125];
    float s[27];
    #pragma unroll
    for (int j = 0; j < 27; j++) {
        int kh = j / 9, kw = (j / 3) % 3, kz = j % 3;
        int nb = ((sh + kh) << 10) + ((sw + kw) << 5) + (sz + kz);
        float4 k4 = *(const float4*)&qkv[(size_t)nb * JQKV + 128 + h * 16 + p * 4];
        float d = qx * k4.x + qy * k4.y + qz * k4.z + qw * k4.w;
        d += __shfl_xor_sync(0xffffffffu, d, 1);
        d += __shfl_xor_sync(0xffffffffu, d, 2);
        s[j] = d + rb[(bh + kh) * 25 + (bw + kw) * 5 + (bz + kz)];
    }

    float mx = -1e30f;
    #pragma unroll
    for (int j = 0; j < 27; j++) mx = fmaxf(mx, s[j]);
    float sum = 0.f;
    #pragma unroll
    for (int j = 0; j < 27; j++) { s[j] = expf(s[j] - mx); sum += s[j]; }
    const float inv = 1.f / sum;

    float ox = 0.f, oy = 0.f, oz = 0.f, ow = 0.f;
    #pragma unroll
    for (int j = 0; j < 27; j++) {
        int kh = j / 9, kw = (j / 3) % 3, kz = j % 3;
        int nb = ((sh + kh) << 10) + ((sw + kw) << 5) + (sz + kz);
        float4 v4 = *(const float4*)&qkv[(size_t)nb * JQKV + 256 + h * 16 + p * 4];
        float pj = s[j] * inv;
        ox = fmaf(pj, v4.x, ox); oy = fmaf(pj, v4.y, oy);
        oz = fmaf(pj, v4.z, oz); ow = fmaf(pj, v4.w, ow);
    }
    *(float4*)&out[(size_t)n * CH + h * 16 + p * 4] = make_float4(ox, oy, oz, ow);
}

// ---------------- per-channel sum/sumsq over tokens ----------------
__global__ void stats_kernel(const float* __restrict__ A, float* __restrict__ gsum,
                             float* __restrict__ gsq)
{
    __shared__ float ssum[CH], ssq[CH];
    const int tid = threadIdx.x;
    if (tid < CH) { ssum[tid] = 0.f; ssq[tid] = 0.f; }
    __syncthreads();
    const int warp = tid >> 5, lane = tid & 31;
    const int n0 = blockIdx.x * 128;
    float ps[4] = {0, 0, 0, 0}, pq[4] = {0, 0, 0, 0};
    for (int r = warp; r < 128; r += 8) {
        const float* row = &A[(size_t)(n0 + r) * CH];
        #pragma unroll
        for (int c = 0; c < 4; c++) {
            float v = row[lane + c * 32];
            ps[c] += v; pq[c] += v * v;
        }
    }
    #pragma unroll
    for (int c = 0; c < 4; c++) {
        atomicAdd(&ssum[lane + c * 32], ps[c]);
        atomicAdd(&ssq[lane + c * 32], pq[c]);
    }
    __syncthreads();
    if (tid < CH) { atomicAdd(&gsum[tid], ssum[tid]); atomicAdd(&gsq[tid], ssq[tid]); }
}

__global__ void finalize_kernel(const float* __restrict__ gsum, const float* __restrict__ gsq,
                                float* __restrict__ mean, float* __restrict__ istd)
{
    int c = threadIdx.x;
    if (c < CH) {
        float m = gsum[c] * (1.f / (float)NTOK);
        float v = gsq[c] * (1.f / (float)NTOK) - m * m;
        mean[c] = m;
        istd[c] = rsqrtf(v + 1e-5f);
    }
}

// ---------------- normalize + transpose (N,C) -> (C,N) ----------------
__global__ void tnorm_kernel(const float* __restrict__ A, const float* __restrict__ mean,
                             const float* __restrict__ istd, float* __restrict__ out)
{
    __shared__ float tile[32][33];
    const int n0 = blockIdx.x * 32, c0 = blockIdx.y * 32;
    const int tx = threadIdx.x, ty = threadIdx.y;  // (32, 8)
    #pragma unroll
    for (int i = 0; i < 4; i++) {
        int nn = ty + i * 8;
        tile[nn][tx] = A[(size_t)(n0 + nn) * CH + c0 + tx];
    }
    __syncthreads();
    #pragma unroll
    for (int i = 0; i < 4; i++) {
        int cc = ty + i * 8;
        int c = c0 + cc;
        out[(size_t)c * NTOK + (n0 + tx)] = (tile[tx][cc] - mean[c]) * istd[c];
    }
}

// ---------------- launch ----------------
extern "C" void kernel_launch(void* const* d_in, const int* in_sizes, int n_in,
                              void* d_out, int out_size)
{
    const float* x      = (const float*)d_in[0];  // (C, N) = (128, 32768)
    const float* w_qkv  = (const float*)d_in[1];  // (384, 128)
    const float* b_qkv  = (const float*)d_in[2];
    const float* rpb    = (const float*)d_in[3];  // (8, 5, 5, 5)
    const float* w_proj = (const float*)d_in[4];  // (128, 128)
    const float* b_proj = (const float*)d_in[5];
    const float* w_ffn1 = (const float*)d_in[6];  // (512, 128)
    const float* b_ffn1 = (const float*)d_in[7];
    const float* w_ffn2 = (const float*)d_in[8];  // (128, 512)
    const float* b_ffn2 = (const float*)d_in[9];
    float* out = (float*)d_out;

    float *p_qkv, *p_attn, *p_y, *p_h, *p_z;
    float *p_sum1, *p_sq1, *p_sum2, *p_sq2, *p_m1, *p_i1, *p_m2, *p_i2;
    uint2 *p_ws;
    cudaGetSymbolAddress((void**)&p_qkv,  g_qkv);
    cudaGetSymbolAddress((void**)&p_attn, g_attn);
    cudaGetSymbolAddress((void**)&p_y,    g_y);
    cudaGetSymbolAddress((void**)&p_h,    g_h);
    cudaGetSymbolAddress((void**)&p_z,    g_z);
    cudaGetSymbolAddress((void**)&p_ws,   g_wsplit);
    cudaGetSymbolAddress((void**)&p_sum1, g_sum1);
    cudaGetSymbolAddress((void**)&p_sq1,  g_sq1);
    cudaGetSymbolAddress((void**)&p_sum2, g_sum2);
    cudaGetSymbolAddress((void**)&p_sq2,  g_sq2);
    cudaGetSymbolAddress((void**)&p_m1,   g_m1);
    cudaGetSymbolAddress((void**)&p_i1,   g_i1);
    cudaGetSymbolAddress((void**)&p_m2,   g_m2);
    cudaGetSymbolAddress((void**)&p_i2,   g_i2);

    zero_stats_kernel<<<1, 128>>>();
    split_weights_kernel<<<(NWSPLIT + 255) / 256, 256>>>(w_qkv, w_proj, w_ffn1, w_ffn2);

    // QKV: A = x (K-major, (128, 32768)) -> g_qkv (N, 384)
    gemm_tc<true, false, 0><<<dim3(NTOK / 128, JQKV / 64), 128>>>(
        x, p_ws + OFF_QKV, b_qkv, p_qkv, NTOK, CH, JQKV, nullptr, nullptr, nullptr);

    // attention -> g_attn (N, 128)
    attn_kernel<<<NTOK / 8, 256>>>(p_qkv, rpb, p_attn);

    // proj: g_attn (N,128) @ w_proj^T -> g_y (N,128)
    gemm_tc<false, false, 0><<<dim3(NTOK / 128, CH / 64), 128>>>(
        p_attn, p_ws + OFF_PROJ, b_proj, p_y, NTOK, CH, CH, nullptr, nullptr, nullptr);

    // instance-norm #1 stats on g_y
    stats_kernel<<<NTOK / 128, 256>>>(p_y, p_sum1, p_sq1);
    finalize_kernel<<<1, 128>>>(p_sum1, p_sq1, p_m1, p_i1);

    // FFN1: normalize(g_y) @ w_ffn1^T, gelu -> g_h (N,512)
    gemm_tc<false, true, 1><<<dim3(NTOK / 128, CF / 64), 128>>>(
        p_y, p_ws + OFF_FFN1, b_ffn1, p_h, NTOK, CH, CF, p_m1, p_i1, nullptr);

    // FFN2: g_h @ w_ffn2^T + bias + normalize(g_y) residual -> g_z (N,128)
    gemm_tc<false, false, 2><<<dim3(NTOK / 128, CH / 64), 128>>>(
        p_h, p_ws + OFF_FFN2, b_ffn2, p_z, NTOK, CF, CH, p_m1, p_i1, p_y);

    // instance-norm #2 stats on g_z
    stats_kernel<<<NTOK / 128, 256>>>(p_z, p_sum2, p_sq2);
    finalize_kernel<<<1, 128>>>(p_sum2, p_sq2, p_m2, p_i2);

    // normalize + transpose to (C, N)
    tnorm_kernel<<<dim3(NTOK / 32, CH / 32), dim3(32, 8)>>>(p_z, p_m2, p_i2, out);
}